// round 8
// baseline (speedup 1.0000x reference)
#include <cuda_runtime.h>
#include <cuda_bf16.h>

#define BATCH  4
#define NB     2048
#define NC     4
#define ROWSL  16          // u16 slots per row: [0]=count, [1..15]=neighbors
#define MAXDEG 15

// __device__ scratch (allocation-free rule). uint4 => 32B-aligned rows.
__device__ uint4 g_adj_raw[(size_t)BATCH * NB * ROWSL / 8];
#define G_ADJ ((unsigned short*)g_adj_raw)
__device__ int g_flag[BATCH];

// ---------------------------------------------------------------------------
// K1: adjacency rows (count + list). 512 blocks x 512 thr, 16 rows/block.
// ---------------------------------------------------------------------------
__global__ void __launch_bounds__(512) adj_kernel(const float4* __restrict__ boxes,
                                                  const float* __restrict__ thrp) {
    __shared__ float4 sbox[NB];
    __shared__ float  sar[NB];
    int b    = blockIdx.x >> 7;
    int tile = blockIdx.x & 127;
    int tid  = threadIdx.x;
    if (blockIdx.x == 0 && tid < BATCH) g_flag[tid] = 0;

    const float4* bb = boxes + (size_t)b * NB;
    for (int i = tid; i < NB; i += 512) {
        float4 v = bb[i];
        sbox[i] = v;
        sar[i] = (v.z - v.x) * (v.w - v.y);
    }
    __syncthreads();

    float thr = thrp[0];
    int warp = tid >> 5, lane = tid & 31;
    int r = tile * 16 + warp;

    float4 rb = sbox[r];
    float rar = sar[r];
    int cnt = 0;
    unsigned short* row = G_ADJ + (size_t)(b * NB + r) * ROWSL;

    #pragma unroll 4
    for (int c = 0; c < NB / 32; c++) {
        int u = c * 32 + lane;
        float4 ub = sbox[u];
        float ix = fminf(rb.z, ub.z) - fmaxf(rb.x, ub.x);
        float iy = fminf(rb.w, ub.w) - fmaxf(rb.y, ub.y);
        ix = fmaxf(ix, 0.0f);
        iy = fmaxf(iy, 0.0f);
        float inter = ix * iy;
        float unim  = fmaxf(rar + sar[u] - inter, 1e-6f);
        bool hit = inter > thr * unim;               // == inter/max(uni,1e-6) > thr
        unsigned word = __ballot_sync(0xffffffffu, hit);
        if (c == (r >> 5)) word &= ~(1u << (r & 31));     // drop self
        if (lane == 0 && word) {
            int base = c * 32;
            while (word) {
                int j = __ffs(word) - 1;
                word &= word - 1u;
                if (cnt < MAXDEG) row[1 + cnt] = (unsigned short)(base + j);
                cnt++;                                // full count even if truncated
            }
        }
    }
    if (lane == 0) row[0] = (unsigned short)cnt;
}

// ---------------------------------------------------------------------------
// K2: block-parallel CC + warp-parallel greedy. grid = BATCH, 1024 thr.
//  - min-label propagation + pointer jumping in smem (O(log) rounds)
//  - count/scan/scatter -> per-component member lists in smem
//  - one warp per component: exact greedy (score desc, tie idx asc) with
//    __reduce_max/min_sync; claims along adjacency rows (<=15 entries).
// deg>MAXDEG -> g_flag[b] (exact fallback rewrites the batch).
// Assumes thr < 1 (self-IoU = 1 > thr => active boxes self-match).
// ---------------------------------------------------------------------------
#define SM_LAB   0                      // 2048 int
#define SM_CNT   8192                   // 2048 int
#define SM_OFFS  16384                  // 2048 int
#define SM_CUR   24576                  // 2048 int
#define SM_SCO   32768                  // 2048 int/float (scan buf, then scores)
#define SM_MEMB  40960                  // 2048 u16
#define SM_ROOTL 45056                  // 1024 u16
#define SM_ACT   47104                  // 2048 u8
#define SM_MISC  49152                  // ints: [0]=changed, [1]=nroots
#define CC_SMEM  (SM_MISC + 32)

__device__ __forceinline__ unsigned flipkey(float s) {
    unsigned u = __float_as_uint(s);
    return (u & 0x80000000u) ? ~u : (u | 0x80000000u);   // total order on floats
}

__global__ void __launch_bounds__(1024) cc_kernel(const float* __restrict__ scores,
                                                  const float* __restrict__ sthrp,
                                                  float* __restrict__ out) {
    extern __shared__ unsigned char sm[];
    int*            lab   = (int*)(sm + SM_LAB);
    int*            cntA  = (int*)(sm + SM_CNT);
    int*            offs  = (int*)(sm + SM_OFFS);
    int*            cur   = (int*)(sm + SM_CUR);
    int*            scoI  = (int*)(sm + SM_SCO);
    float*          scoF  = (float*)(sm + SM_SCO);
    unsigned short* memb  = (unsigned short*)(sm + SM_MEMB);
    unsigned short* rootl = (unsigned short*)(sm + SM_ROOTL);
    unsigned char*  act   = sm + SM_ACT;
    int*            misc  = (int*)(sm + SM_MISC);

    int b   = blockIdx.x;
    int tid = threadIdx.x;
    float sthr = sthrp[0];
    if (tid == 0) misc[1] = 0;

    int v0 = tid, v1 = tid + 1024;
    const unsigned short* row0 = G_ADJ + (size_t)(b * NB + v0) * ROWSL;
    const unsigned short* row1 = G_ADJ + (size_t)(b * NB + v1) * ROWSL;
    int d0 = row0[0], d1 = row1[0];
    if (d0 > MAXDEG || d1 > MAXDEG) { g_flag[b] = 1; d0 = min(d0, MAXDEG); d1 = min(d1, MAXDEG); }

    lab[v0] = v0;
    lab[v1] = v1;

    // Isolated nodes: trivial outputs (independent of smem phases).
    if (d0 == 0) {
        #pragma unroll
        for (int c = 0; c < NC; c++) {
            size_t g = (size_t)(b * NC + c) * NB + v0;
            out[g] = (scores[g] > sthr) ? (float)v0 : -1.0f;
        }
    }
    if (d1 == 0) {
        #pragma unroll
        for (int c = 0; c < NC; c++) {
            size_t g = (size_t)(b * NC + c) * NB + v1;
            out[g] = (scores[g] > sthr) ? (float)v1 : -1.0f;
        }
    }

    // --- min-label propagation + pointer jumping (monotone; races safe) ---
    for (int round = 0; round < 4096; round++) {
        __syncthreads();
        if (tid == 0) misc[0] = 0;
        __syncthreads();
        if (d0 > 0) {
            int m = lab[v0];
            for (int e = 1; e <= d0; e++) m = min(m, lab[row0[e]]);
            m = min(m, lab[m]);
            if (m < lab[v0]) { lab[v0] = m; misc[0] = 1; }
        }
        if (d1 > 0) {
            int m = lab[v1];
            for (int e = 1; e <= d1; e++) m = min(m, lab[row1[e]]);
            m = min(m, lab[m]);
            if (m < lab[v1]) { lab[v1] = m; misc[0] = 1; }
        }
        __syncthreads();
        if (d0 > 0) { int l = lab[v0], l2 = lab[l]; if (l2 < l) { lab[v0] = l2; misc[0] = 1; } }
        if (d1 > 0) { int l = lab[v1], l2 = lab[l]; if (l2 < l) { lab[v1] = l2; misc[0] = 1; } }
        __syncthreads();
        if (!misc[0]) break;
    }

    // --- count members per root ---
    cntA[v0] = 0; cntA[v1] = 0;
    __syncthreads();
    if (d0 > 0) atomicAdd(&cntA[lab[v0]], 1);
    if (d1 > 0) atomicAdd(&cntA[lab[v1]], 1);
    __syncthreads();

    // --- exclusive scan (Hillis-Steele, ping-pong offs<->scoI) ---
    offs[v0] = cntA[v0]; offs[v1] = cntA[v1];
    __syncthreads();
    int* A = offs; int* Bf = scoI;
    for (int dstep = 1; dstep < NB; dstep <<= 1) {
        Bf[v0] = A[v0] + ((v0 >= dstep) ? A[v0 - dstep] : 0);
        Bf[v1] = A[v1] + ((v1 >= dstep) ? A[v1 - dstep] : 0);
        __syncthreads();
        int* t = A; A = Bf; Bf = t;
    }
    {
        int e0 = A[v0] - cntA[v0], e1 = A[v1] - cntA[v1];
        __syncthreads();                 // A may alias offs; settle reads first
        offs[v0] = e0; cur[v0] = e0;
        offs[v1] = e1; cur[v1] = e1;
    }
    __syncthreads();

    // --- scatter members; collect roots ---
    if (d0 > 0) {
        int r = lab[v0];
        memb[atomicAdd(&cur[r], 1)] = (unsigned short)v0;
        if (r == v0) rootl[atomicAdd(&misc[1], 1)] = (unsigned short)v0;
    }
    if (d1 > 0) {
        int r = lab[v1];
        memb[atomicAdd(&cur[r], 1)] = (unsigned short)v1;
        if (r == v1) rootl[atomicAdd(&misc[1], 1)] = (unsigned short)v1;
    }
    __syncthreads();
    int nroots = misc[1];

    // --- warp-parallel greedy, one warp per component ---
    int warp = tid >> 5, lane = tid & 31;
    for (int ci = warp; ci < nroots; ci += 32) {
        int r    = rootl[ci];
        int base = offs[r];
        int cnt  = cntA[r];
        for (int c = 0; c < NC; c++) {
            const float* spc = scores + (size_t)(b * NC + c) * NB;
            float*       opc = out + (size_t)(b * NC + c) * NB;
            for (int k = lane; k < cnt; k += 32) {
                int e = memb[base + k];
                float s = spc[e];
                if (s > sthr) { act[base + k] = 1; scoF[base + k] = s; }
                else          { act[base + k] = 0; opc[e] = -1.0f; }
            }
            __syncwarp();
            for (;;) {
                unsigned mk = 0u;
                for (int k = lane; k < cnt; k += 32)
                    if (act[base + k]) mk = max(mk, flipkey(scoF[base + k]));
                unsigned M = __reduce_max_sync(0xffffffffu, mk);
                if (M == 0u) break;
                unsigned mi = 0xFFFFFFFFu;
                for (int k = lane; k < cnt; k += 32)
                    if (act[base + k] && flipkey(scoF[base + k]) == M)
                        mi = min(mi, (unsigned)memb[base + k]);
                int bi = (int)__reduce_min_sync(0xffffffffu, mi);

                const unsigned short* brow = G_ADJ + (size_t)(b * NB + bi) * ROWSL;
                int dv = min((int)brow[0], MAXDEG);
                float lf = (float)bi;
                for (int k = lane; k < cnt; k += 32) {
                    if (act[base + k]) {
                        int e = memb[base + k];
                        bool hit = (e == bi);
                        for (int t = 1; t <= dv; t++) hit |= (e == (int)brow[t]);
                        if (hit) { act[base + k] = 0; opc[e] = lf; }
                    }
                }
                __syncwarp();
            }
        }
    }
}

// ---------------------------------------------------------------------------
// K3: exact serial fallback per batch; early-exits unless g_flag[b] set.
// ---------------------------------------------------------------------------
#define K3_SBOX 0
#define K3_SAR  32768
#define K3_SUP  40960
#define K3_SMEM (K3_SUP + NC * NB)

__global__ void __launch_bounds__(1024) fb_kernel(const float4* __restrict__ boxes,
                                                  const float* __restrict__ scores,
                                                  const float* __restrict__ thrp,
                                                  const float* __restrict__ sthrp,
                                                  float* __restrict__ out) {
    int b = blockIdx.x;
    if (g_flag[b] == 0) return;

    extern __shared__ unsigned char sm[];
    float4*        sbox = (float4*)(sm + K3_SBOX);
    float*         sar  = (float*)(sm + K3_SAR);
    unsigned char* sup  = sm + K3_SUP;

    int tid = threadIdx.x;
    float thr = thrp[0], sthr = sthrp[0];
    const float4* bb = boxes + (size_t)b * NB;
    for (int i = tid; i < NB; i += 1024) {
        float4 v = bb[i];
        sbox[i] = v;
        sar[i] = (v.z - v.x) * (v.w - v.y);
    }
    for (int idx = tid; idx < NC * NB; idx += 1024) {
        int c = idx >> 11, n = idx & (NB - 1);
        size_t g = (size_t)(b * NC + c) * NB + n;
        sup[idx] = (scores[g] > sthr) ? 0 : 1;
        out[g] = -1.0f;
    }
    __syncthreads();

    int warp = tid >> 5, lane = tid & 31;
    if (warp < NC) {
        int c = warp;
        volatile unsigned char* supc = sup + (c << 11);
        const float* spc = scores + (size_t)(b * NC + c) * NB;
        float*       opc = out + (size_t)(b * NC + c) * NB;
        for (;;) {
            float bs = -1e30f; int bi = 1 << 30;
            for (int k = 0; k < NB / 32; k++) {
                int u = k * 32 + lane;
                if (!supc[u]) {
                    float s = spc[u];
                    if (s > bs || (s == bs && u < bi)) { bs = s; bi = u; }
                }
            }
            #pragma unroll
            for (int off = 16; off; off >>= 1) {
                float os = __shfl_down_sync(0xffffffffu, bs, off);
                int   oi = __shfl_down_sync(0xffffffffu, bi, off);
                if (os > bs || (os == bs && oi < bi)) { bs = os; bi = oi; }
            }
            bi = __shfl_sync(0xffffffffu, bi, 0);
            if (bi >= (1 << 30)) break;

            float4 tb = sbox[bi];
            float tar = sar[bi];
            float lf = (float)bi;
            for (int k = 0; k < NB / 32; k++) {
                int u = k * 32 + lane;
                if (!supc[u]) {
                    float4 ub = sbox[u];
                    float ix = fminf(tb.z, ub.z) - fmaxf(tb.x, ub.x);
                    float iy = fminf(tb.w, ub.w) - fmaxf(tb.y, ub.y);
                    ix = fmaxf(ix, 0.0f);
                    iy = fmaxf(iy, 0.0f);
                    float inter = ix * iy;
                    float unim  = fmaxf(tar + sar[u] - inter, 1e-6f);
                    if (inter > thr * unim) { supc[u] = 1; opc[u] = lf; }
                }
            }
            if (lane == 0) supc[bi] = 1;
            __syncwarp();
        }
    }
}

// ---------------------------------------------------------------------------
extern "C" void kernel_launch(void* const* d_in, const int* in_sizes, int n_in,
                              void* d_out, int out_size) {
    const float4* boxes  = (const float4*)d_in[0];
    const float*  scores = (const float*)d_in[1];
    const float*  iouthr = (const float*)d_in[2];
    const float*  scothr = (const float*)d_in[3];
    float* out = (float*)d_out;

    cudaFuncSetAttribute(cc_kernel, cudaFuncAttributeMaxDynamicSharedMemorySize, CC_SMEM);
    cudaFuncSetAttribute(fb_kernel, cudaFuncAttributeMaxDynamicSharedMemorySize, K3_SMEM);

    adj_kernel<<<BATCH * 128, 512>>>(boxes, iouthr);
    cc_kernel<<<BATCH, 1024, CC_SMEM>>>(scores, scothr, out);
    fb_kernel<<<BATCH, 1024, K3_SMEM>>>(boxes, scores, iouthr, scothr, out);
}

// round 9
// speedup vs baseline: 1.1783x; 1.1783x over previous
#include <cuda_runtime.h>
#include <cuda_bf16.h>

#define BATCH  4
#define NB     2048
#define NC     4
#define ROWSL  16          // u16 slots per row: [0]=count, [1..15]=neighbors
#define MAXDEG 15

// __device__ scratch (allocation-free rule). uint4 => 32B-aligned rows.
__device__ uint4 g_adj_raw[(size_t)BATCH * NB * ROWSL / 8];
#define G_ADJ ((unsigned short*)g_adj_raw)
__device__ int g_flag[BATCH];

// ---------------------------------------------------------------------------
// K1: adjacency rows (count + list). 512 blocks x 512 thr, 16 rows/block.
// ---------------------------------------------------------------------------
__global__ void __launch_bounds__(512) adj_kernel(const float4* __restrict__ boxes,
                                                  const float* __restrict__ thrp) {
    __shared__ float4 sbox[NB];
    __shared__ float  sar[NB];
    int b    = blockIdx.x >> 7;
    int tile = blockIdx.x & 127;
    int tid  = threadIdx.x;
    if (blockIdx.x == 0 && tid < BATCH) g_flag[tid] = 0;

    const float4* bb = boxes + (size_t)b * NB;
    for (int i = tid; i < NB; i += 512) {
        float4 v = bb[i];
        sbox[i] = v;
        sar[i] = (v.z - v.x) * (v.w - v.y);
    }
    __syncthreads();

    float thr = thrp[0];
    int warp = tid >> 5, lane = tid & 31;
    int r = tile * 16 + warp;

    float4 rb = sbox[r];
    float rar = sar[r];
    int cnt = 0;
    unsigned short* row = G_ADJ + (size_t)(b * NB + r) * ROWSL;

    #pragma unroll 4
    for (int c = 0; c < NB / 32; c++) {
        int u = c * 32 + lane;
        float4 ub = sbox[u];
        float ix = fminf(rb.z, ub.z) - fmaxf(rb.x, ub.x);
        float iy = fminf(rb.w, ub.w) - fmaxf(rb.y, ub.y);
        ix = fmaxf(ix, 0.0f);
        iy = fmaxf(iy, 0.0f);
        float inter = ix * iy;
        float unim  = fmaxf(rar + sar[u] - inter, 1e-6f);
        bool hit = inter > thr * unim;               // == inter/max(uni,1e-6) > thr
        unsigned word = __ballot_sync(0xffffffffu, hit);
        if (c == (r >> 5)) word &= ~(1u << (r & 31));     // drop self
        if (lane == 0 && word) {
            int base = c * 32;
            while (word) {
                int j = __ffs(word) - 1;
                word &= word - 1u;
                if (cnt < MAXDEG) row[1 + cnt] = (unsigned short)(base + j);
                cnt++;                                // full count even if truncated
            }
        }
    }
    if (lane == 0) row[0] = (unsigned short)cnt;
}

// ---------------------------------------------------------------------------
// K2: lex-first-MIS greedy. grid = BATCH*NC, 1024 thr.
// Leaders of greedy NMS-match == lex-first MIS under (score desc, idx asc);
// match of a claimed box == its highest-priority adjacent leader.
// Monotone fixpoint rounds over smem-staged adjacency; terminates because the
// max-priority undecided node always decides each synchronized round.
// Status: 0=undecided(active) 1=leader 2=out(claimed,active) 3=done/ignore.
// deg>MAXDEG -> g_flag[b], block aborts (fb rewrites the whole batch).
// ---------------------------------------------------------------------------
#define MS_ROW  0                       // 2048*16 u16 = 64KB
#define MS_KEY  65536                   // 2048 u32
#define MS_ST   73728                   // 2048 u8
#define MS_CNT  75776                   // 2 ints: [0]=not-done flag, [1]=deg-ovf
#define MS_SMEM 75808

__device__ __forceinline__ unsigned flipkey(float s) {
    unsigned u = __float_as_uint(s);
    return (u & 0x80000000u) ? ~u : (u | 0x80000000u);   // total order on floats
}

__global__ void __launch_bounds__(1024) mis_kernel(const float* __restrict__ scores,
                                                   const float* __restrict__ thrp,
                                                   const float* __restrict__ sthrp,
                                                   float* __restrict__ out) {
    extern __shared__ unsigned char sm[];
    unsigned short*         srow = (unsigned short*)(sm + MS_ROW);
    unsigned*               skey = (unsigned*)(sm + MS_KEY);
    volatile unsigned char* sst  = sm + MS_ST;
    volatile int*           scnt = (int*)(sm + MS_CNT);

    int bc = blockIdx.x, b = bc >> 2;
    int tid = threadIdx.x, lane = tid & 31;
    float sthr = sthrp[0];
    bool selfm = thrp[0] < 1.0f;        // self-IoU = 1 claims self iff thr < 1
    const float* spc = scores + (size_t)bc * NB;
    float*       opc = out + (size_t)bc * NB;

    // Stage adjacency rows (64KB) into smem.
    const uint4* gr = (const uint4*)(G_ADJ + (size_t)b * NB * ROWSL);
    uint4* sr4 = (uint4*)srow;
    for (int k = tid; k < NB * ROWSL / 8; k += 1024) sr4[k] = gr[k];
    if (tid == 0) { scnt[0] = 0; scnt[1] = 0; }
    __syncthreads();

    // Init: keys, status, trivial outputs.
    for (int n = tid; n < NB; n += 1024) {
        float s = spc[n];
        skey[n] = flipkey(s);
        int deg = srow[n * ROWSL];
        unsigned char st;
        if (s > sthr) {
            if (deg > MAXDEG)      { scnt[1] = 1; st = 3; }
            else if (deg == 0)     { st = 3; opc[n] = selfm ? (float)n : -1.0f; }
            else                   st = 0;
        } else { st = 3; opc[n] = -1.0f; }
        sst[n] = st;
    }
    __syncthreads();
    if (scnt[1]) { if (tid == 0) g_flag[b] = 1; return; }

    // Fixpoint rounds.
    for (int round = 0; round < 4096; round++) {
        bool have = false;
        for (int n = tid; n < NB; n += 1024) {
            if (sst[n] != 0) continue;
            const unsigned short* row = srow + n * ROWSL;
            int deg = row[0];
            unsigned mk = skey[n];
            bool blocked = false, claimed = false;
            for (int e = 1; e <= deg; e++) {
                int u = row[e];
                unsigned char stu = sst[u];
                if (stu >= 2) continue;                 // out/ignored: no effect
                unsigned fu = skey[u];
                bool hp = (fu > mk) || (fu == mk && u < n);
                if (!hp) continue;
                if (stu == 1) { claimed = true; break; } // hp leader -> out
                blocked = true;                          // hp undecided -> wait
            }
            if (claimed)       sst[n] = 2;
            else if (!blocked) sst[n] = 1;
            else have = true;
        }
        unsigned anyw = __ballot_sync(0xffffffffu, have);
        if (lane == 0 && anyw) scnt[0] = 1;
        __syncthreads();
        if (scnt[0] == 0) break;
        __syncthreads();
        if (tid == 0) scnt[0] = 0;
        __syncthreads();
    }

    // Final assignment.
    __syncthreads();
    for (int n = tid; n < NB; n += 1024) {
        unsigned char st = sst[n];
        if (st == 1) {
            opc[n] = (float)n;
        } else if (st == 2) {
            const unsigned short* row = srow + n * ROWSL;
            int deg = row[0];
            unsigned bk = 0; int bu = -1;
            for (int e = 1; e <= deg; e++) {
                int u = row[e];
                if (sst[u] == 1) {
                    unsigned fu = skey[u];
                    if (bu < 0 || fu > bk || (fu == bk && u < bu)) { bk = fu; bu = u; }
                }
            }
            opc[n] = (float)bu;        // >=1 leader neighbor guaranteed
        }
    }
}

// ---------------------------------------------------------------------------
// K3: exact serial fallback per batch; early-exits unless g_flag[b] set.
// ---------------------------------------------------------------------------
#define K3_SBOX 0
#define K3_SAR  32768
#define K3_SUP  40960
#define K3_SMEM (K3_SUP + NC * NB)

__global__ void __launch_bounds__(1024) fb_kernel(const float4* __restrict__ boxes,
                                                  const float* __restrict__ scores,
                                                  const float* __restrict__ thrp,
                                                  const float* __restrict__ sthrp,
                                                  float* __restrict__ out) {
    int b = blockIdx.x;
    if (g_flag[b] == 0) return;

    extern __shared__ unsigned char sm[];
    float4*        sbox = (float4*)(sm + K3_SBOX);
    float*         sar  = (float*)(sm + K3_SAR);
    unsigned char* sup  = sm + K3_SUP;

    int tid = threadIdx.x;
    float thr = thrp[0], sthr = sthrp[0];
    const float4* bb = boxes + (size_t)b * NB;
    for (int i = tid; i < NB; i += 1024) {
        float4 v = bb[i];
        sbox[i] = v;
        sar[i] = (v.z - v.x) * (v.w - v.y);
    }
    for (int idx = tid; idx < NC * NB; idx += 1024) {
        int c = idx >> 11, n = idx & (NB - 1);
        size_t g = (size_t)(b * NC + c) * NB + n;
        sup[idx] = (scores[g] > sthr) ? 0 : 1;
        out[g] = -1.0f;
    }
    __syncthreads();

    int warp = tid >> 5, lane = tid & 31;
    if (warp < NC) {
        int c = warp;
        volatile unsigned char* supc = sup + (c << 11);
        const float* spc = scores + (size_t)(b * NC + c) * NB;
        float*       opc = out + (size_t)(b * NC + c) * NB;
        for (;;) {
            float bs = -1e30f; int bi = 1 << 30;
            for (int k = 0; k < NB / 32; k++) {
                int u = k * 32 + lane;
                if (!supc[u]) {
                    float s = spc[u];
                    if (s > bs || (s == bs && u < bi)) { bs = s; bi = u; }
                }
            }
            #pragma unroll
            for (int off = 16; off; off >>= 1) {
                float os = __shfl_down_sync(0xffffffffu, bs, off);
                int   oi = __shfl_down_sync(0xffffffffu, bi, off);
                if (os > bs || (os == bs && oi < bi)) { bs = os; bi = oi; }
            }
            bi = __shfl_sync(0xffffffffu, bi, 0);
            if (bi >= (1 << 30)) break;

            float4 tb = sbox[bi];
            float tar = sar[bi];
            float lf = (float)bi;
            for (int k = 0; k < NB / 32; k++) {
                int u = k * 32 + lane;
                if (!supc[u]) {
                    float4 ub = sbox[u];
                    float ix = fminf(tb.z, ub.z) - fmaxf(tb.x, ub.x);
                    float iy = fminf(tb.w, ub.w) - fmaxf(tb.y, ub.y);
                    ix = fmaxf(ix, 0.0f);
                    iy = fmaxf(iy, 0.0f);
                    float inter = ix * iy;
                    float unim  = fmaxf(tar + sar[u] - inter, 1e-6f);
                    if (inter > thr * unim) { supc[u] = 1; opc[u] = lf; }
                }
            }
            if (lane == 0) supc[bi] = 1;
            __syncwarp();
        }
    }
}

// ---------------------------------------------------------------------------
extern "C" void kernel_launch(void* const* d_in, const int* in_sizes, int n_in,
                              void* d_out, int out_size) {
    const float4* boxes  = (const float4*)d_in[0];
    const float*  scores = (const float*)d_in[1];
    const float*  iouthr = (const float*)d_in[2];
    const float*  scothr = (const float*)d_in[3];
    float* out = (float*)d_out;

    cudaFuncSetAttribute(mis_kernel, cudaFuncAttributeMaxDynamicSharedMemorySize, MS_SMEM);
    cudaFuncSetAttribute(fb_kernel, cudaFuncAttributeMaxDynamicSharedMemorySize, K3_SMEM);

    adj_kernel<<<BATCH * 128, 512>>>(boxes, iouthr);
    mis_kernel<<<BATCH * NC, 1024, MS_SMEM>>>(scores, iouthr, scothr, out);
    fb_kernel<<<BATCH, 1024, K3_SMEM>>>(boxes, scores, iouthr, scothr, out);
}

// round 10
// speedup vs baseline: 1.4480x; 1.2289x over previous
#include <cuda_runtime.h>
#include <cuda_bf16.h>

#define BATCH  4
#define NB     2048
#define NC     4
#define ROWSL  16          // u16 slots per row: [0]=count, [1..15]=neighbors
#define MAXDEG 15
#define NBINS  64

// __device__ scratch (allocation-free rule). uint4 => 32B-aligned rows.
__device__ uint4 g_adj_raw[(size_t)BATCH * NB * ROWSL / 8];
#define G_ADJ ((unsigned short*)g_adj_raw)
__device__ int            g_flag[BATCH];
__device__ float4         g_sbox[BATCH * NB];      // x1-sorted boxes
__device__ unsigned short g_sidx[BATCH * NB];      // sorted pos -> original idx
__device__ int            g_binoff[BATCH][NBINS + 1];
__device__ float          g_meta[BATCH][3];        // minx, scale, wmax

// ---------------------------------------------------------------------------
// K0: per-batch x1 counting sort into NBINS bins. grid = BATCH, 1024 thr.
// ---------------------------------------------------------------------------
__global__ void __launch_bounds__(1024) sort_kernel(const float4* __restrict__ boxes) {
    __shared__ int   hist[NBINS], cur[NBINS], boff[NBINS + 1];
    __shared__ float rmin[32], rmax[32], rw[32];
    __shared__ float s_minx, s_scale;

    int b = blockIdx.x, tid = threadIdx.x;
    int lane = tid & 31, warp = tid >> 5;
    if (tid == 0) g_flag[b] = 0;
    if (tid < NBINS) { hist[tid] = 0; cur[tid] = 0; }

    const float4* bb = boxes + (size_t)b * NB;
    float4 v0 = bb[tid], v1 = bb[tid + 1024];

    // block reduce: min x1, max x1, max width
    float mn = fminf(v0.x, v1.x);
    float mx = fmaxf(v0.x, v1.x);
    float w  = fmaxf(v0.z - v0.x, v1.z - v1.x);
    #pragma unroll
    for (int o = 16; o; o >>= 1) {
        mn = fminf(mn, __shfl_xor_sync(0xffffffffu, mn, o));
        mx = fmaxf(mx, __shfl_xor_sync(0xffffffffu, mx, o));
        w  = fmaxf(w,  __shfl_xor_sync(0xffffffffu, w,  o));
    }
    if (lane == 0) { rmin[warp] = mn; rmax[warp] = mx; rw[warp] = w; }
    __syncthreads();
    if (warp == 0) {
        mn = rmin[lane]; mx = rmax[lane]; w = rw[lane];
        #pragma unroll
        for (int o = 16; o; o >>= 1) {
            mn = fminf(mn, __shfl_xor_sync(0xffffffffu, mn, o));
            mx = fmaxf(mx, __shfl_xor_sync(0xffffffffu, mx, o));
            w  = fmaxf(w,  __shfl_xor_sync(0xffffffffu, w,  o));
        }
        if (lane == 0) {
            s_minx  = mn;
            s_scale = (float)NBINS / fmaxf(mx - mn, 1e-20f);
            g_meta[b][0] = mn;
            g_meta[b][1] = s_scale;
            g_meta[b][2] = fmaxf(w, 0.0f);
        }
    }
    __syncthreads();

    float minx = s_minx, scale = s_scale;
    int bin0 = min(NBINS - 1, max(0, (int)((v0.x - minx) * scale)));
    int bin1 = min(NBINS - 1, max(0, (int)((v1.x - minx) * scale)));
    atomicAdd(&hist[bin0], 1);
    atomicAdd(&hist[bin1], 1);
    __syncthreads();

    if (tid == 0) {
        int acc = 0;
        for (int k = 0; k < NBINS; k++) { boff[k] = acc; acc += hist[k]; }
        boff[NBINS] = acc;
        for (int k = 0; k <= NBINS; k++) g_binoff[b][k] = boff[k];
    }
    __syncthreads();

    int p0 = boff[bin0] + atomicAdd(&cur[bin0], 1);
    g_sbox[b * NB + p0] = v0;
    g_sidx[b * NB + p0] = (unsigned short)tid;
    int p1 = boff[bin1] + atomicAdd(&cur[bin1], 1);
    g_sbox[b * NB + p1] = v1;
    g_sidx[b * NB + p1] = (unsigned short)(tid + 1024);
}

// ---------------------------------------------------------------------------
// K1: adjacency rows over x1-sorted boxes with bin-window pruning.
// 512 blocks x 512 thr, 16 sorted rows/block (warp-per-row). Rows are written
// at ORIGINAL indices, so downstream kernels are unchanged.
// ---------------------------------------------------------------------------
__global__ void __launch_bounds__(512) adj_kernel(const float* __restrict__ thrp) {
    __shared__ float sx1[NB], sy1[NB], sx2[NB], sy2[NB], sar[NB];
    __shared__ unsigned short ssidx[NB];
    __shared__ int sboff[NBINS + 1];

    int b    = blockIdx.x >> 7;
    int tile = blockIdx.x & 127;
    int tid  = threadIdx.x;

    const float4* sb = g_sbox + (size_t)b * NB;
    for (int i = tid; i < NB; i += 512) {
        float4 v = sb[i];
        sx1[i] = v.x; sy1[i] = v.y; sx2[i] = v.z; sy2[i] = v.w;
        sar[i] = (v.z - v.x) * (v.w - v.y);
        ssidx[i] = g_sidx[b * NB + i];
    }
    if (tid <= NBINS) sboff[tid] = g_binoff[b][tid];
    __syncthreads();

    float thr  = thrp[0];
    float minx = g_meta[b][0], scale = g_meta[b][1], wmax = g_meta[b][2];
    bool windowed = (thr >= 0.0f);       // hit => x-overlap only valid for thr>=0

    int warp = tid >> 5, lane = tid & 31;
    int p = tile * 16 + warp;            // sorted position of this row

    float rx1 = sx1[p], ry1 = sy1[p], rx2 = sx2[p], ry2 = sy2[p], rar = sar[p];
    int orr = ssidx[p];
    unsigned short* row = G_ADJ + (size_t)(b * NB + orr) * ROWSL;
    int cnt = 0;

    int c0 = 0;
    if (windowed) {
        int bl = (int)((rx1 - wmax - minx) * scale) - 1;   // -1: float slack
        bl = min(NBINS - 1, max(0, bl));
        c0 = sboff[bl] >> 5;
    }

    for (int c = c0; c < NB / 32; c++) {
        if (windowed && sx1[c * 32] > rx2) break;          // sorted: no more overlap
        int u = c * 32 + lane;
        float ix = fminf(rx2, sx2[u]) - fmaxf(rx1, sx1[u]);
        float iy = fminf(ry2, sy2[u]) - fmaxf(ry1, sy1[u]);
        ix = fmaxf(ix, 0.0f);
        iy = fmaxf(iy, 0.0f);
        float inter = ix * iy;
        float unim  = fmaxf(rar + sar[u] - inter, 1e-6f);
        bool hit = (inter > thr * unim) && (u != p);       // drop self by position
        unsigned word = __ballot_sync(0xffffffffu, hit);
        if (lane == 0 && word) {
            int base = c * 32;
            while (word) {
                int j = __ffs(word) - 1;
                word &= word - 1u;
                if (cnt < MAXDEG) row[1 + cnt] = ssidx[base + j];
                cnt++;                                      // exact count even if truncated
            }
        }
    }
    if (lane == 0) row[0] = (unsigned short)cnt;
}

// ---------------------------------------------------------------------------
// K2: lex-first-MIS greedy. grid = BATCH*NC, 1024 thr. (Unchanged from R9.)
// ---------------------------------------------------------------------------
#define MS_ROW  0                       // 2048*16 u16 = 64KB
#define MS_KEY  65536                   // 2048 u32
#define MS_ST   73728                   // 2048 u8
#define MS_CNT  75776                   // 2 ints: [0]=not-done flag, [1]=deg-ovf
#define MS_SMEM 75808

__device__ __forceinline__ unsigned flipkey(float s) {
    unsigned u = __float_as_uint(s);
    return (u & 0x80000000u) ? ~u : (u | 0x80000000u);   // total order on floats
}

__global__ void __launch_bounds__(1024) mis_kernel(const float* __restrict__ scores,
                                                   const float* __restrict__ thrp,
                                                   const float* __restrict__ sthrp,
                                                   float* __restrict__ out) {
    extern __shared__ unsigned char sm[];
    unsigned short*         srow = (unsigned short*)(sm + MS_ROW);
    unsigned*               skey = (unsigned*)(sm + MS_KEY);
    volatile unsigned char* sst  = sm + MS_ST;
    volatile int*           scnt = (int*)(sm + MS_CNT);

    int bc = blockIdx.x, b = bc >> 2;
    int tid = threadIdx.x, lane = tid & 31;
    float sthr = sthrp[0];
    bool selfm = thrp[0] < 1.0f;        // self-IoU = 1 claims self iff thr < 1
    const float* spc = scores + (size_t)bc * NB;
    float*       opc = out + (size_t)bc * NB;

    const uint4* gr = (const uint4*)(G_ADJ + (size_t)b * NB * ROWSL);
    uint4* sr4 = (uint4*)srow;
    for (int k = tid; k < NB * ROWSL / 8; k += 1024) sr4[k] = gr[k];
    if (tid == 0) { scnt[0] = 0; scnt[1] = 0; }
    __syncthreads();

    for (int n = tid; n < NB; n += 1024) {
        float s = spc[n];
        skey[n] = flipkey(s);
        int deg = srow[n * ROWSL];
        unsigned char st;
        if (s > sthr) {
            if (deg > MAXDEG)      { scnt[1] = 1; st = 3; }
            else if (deg == 0)     { st = 3; opc[n] = selfm ? (float)n : -1.0f; }
            else                   st = 0;
        } else { st = 3; opc[n] = -1.0f; }
        sst[n] = st;
    }
    __syncthreads();
    if (scnt[1]) { if (tid == 0) g_flag[b] = 1; return; }

    for (int round = 0; round < 4096; round++) {
        bool have = false;
        for (int n = tid; n < NB; n += 1024) {
            if (sst[n] != 0) continue;
            const unsigned short* row = srow + n * ROWSL;
            int deg = row[0];
            unsigned mk = skey[n];
            bool blocked = false, claimed = false;
            for (int e = 1; e <= deg; e++) {
                int u = row[e];
                unsigned char stu = sst[u];
                if (stu >= 2) continue;
                unsigned fu = skey[u];
                bool hp = (fu > mk) || (fu == mk && u < n);
                if (!hp) continue;
                if (stu == 1) { claimed = true; break; }
                blocked = true;
            }
            if (claimed)       sst[n] = 2;
            else if (!blocked) sst[n] = 1;
            else have = true;
        }
        unsigned anyw = __ballot_sync(0xffffffffu, have);
        if (lane == 0 && anyw) scnt[0] = 1;
        __syncthreads();
        if (scnt[0] == 0) break;
        __syncthreads();
        if (tid == 0) scnt[0] = 0;
        __syncthreads();
    }

    __syncthreads();
    for (int n = tid; n < NB; n += 1024) {
        unsigned char st = sst[n];
        if (st == 1) {
            opc[n] = (float)n;
        } else if (st == 2) {
            const unsigned short* row = srow + n * ROWSL;
            int deg = row[0];
            unsigned bk = 0; int bu = -1;
            for (int e = 1; e <= deg; e++) {
                int u = row[e];
                if (sst[u] == 1) {
                    unsigned fu = skey[u];
                    if (bu < 0 || fu > bk || (fu == bk && u < bu)) { bk = fu; bu = u; }
                }
            }
            opc[n] = (float)bu;        // >=1 leader neighbor guaranteed
        }
    }
}

// ---------------------------------------------------------------------------
// K3: exact serial fallback per batch; early-exits unless g_flag[b] set.
// ---------------------------------------------------------------------------
#define K3_SBOX 0
#define K3_SAR  32768
#define K3_SUP  40960
#define K3_SMEM (K3_SUP + NC * NB)

__global__ void __launch_bounds__(1024) fb_kernel(const float4* __restrict__ boxes,
                                                  const float* __restrict__ scores,
                                                  const float* __restrict__ thrp,
                                                  const float* __restrict__ sthrp,
                                                  float* __restrict__ out) {
    int b = blockIdx.x;
    if (g_flag[b] == 0) return;

    extern __shared__ unsigned char sm[];
    float4*        sbox = (float4*)(sm + K3_SBOX);
    float*         sar  = (float*)(sm + K3_SAR);
    unsigned char* sup  = sm + K3_SUP;

    int tid = threadIdx.x;
    float thr = thrp[0], sthr = sthrp[0];
    const float4* bb = boxes + (size_t)b * NB;
    for (int i = tid; i < NB; i += 1024) {
        float4 v = bb[i];
        sbox[i] = v;
        sar[i] = (v.z - v.x) * (v.w - v.y);
    }
    for (int idx = tid; idx < NC * NB; idx += 1024) {
        int c = idx >> 11, n = idx & (NB - 1);
        size_t g = (size_t)(b * NC + c) * NB + n;
        sup[idx] = (scores[g] > sthr) ? 0 : 1;
        out[g] = -1.0f;
    }
    __syncthreads();

    int warp = tid >> 5, lane = tid & 31;
    if (warp < NC) {
        int c = warp;
        volatile unsigned char* supc = sup + (c << 11);
        const float* spc = scores + (size_t)(b * NC + c) * NB;
        float*       opc = out + (size_t)(b * NC + c) * NB;
        for (;;) {
            float bs = -1e30f; int bi = 1 << 30;
            for (int k = 0; k < NB / 32; k++) {
                int u = k * 32 + lane;
                if (!supc[u]) {
                    float s = spc[u];
                    if (s > bs || (s == bs && u < bi)) { bs = s; bi = u; }
                }
            }
            #pragma unroll
            for (int off = 16; off; off >>= 1) {
                float os = __shfl_down_sync(0xffffffffu, bs, off);
                int   oi = __shfl_down_sync(0xffffffffu, bi, off);
                if (os > bs || (os == bs && oi < bi)) { bs = os; bi = oi; }
            }
            bi = __shfl_sync(0xffffffffu, bi, 0);
            if (bi >= (1 << 30)) break;

            float4 tb = sbox[bi];
            float tar = sar[bi];
            float lf = (float)bi;
            for (int k = 0; k < NB / 32; k++) {
                int u = k * 32 + lane;
                if (!supc[u]) {
                    float4 ub = sbox[u];
                    float ix = fminf(tb.z, ub.z) - fmaxf(tb.x, ub.x);
                    float iy = fminf(tb.w, ub.w) - fmaxf(tb.y, ub.y);
                    ix = fmaxf(ix, 0.0f);
                    iy = fmaxf(iy, 0.0f);
                    float inter = ix * iy;
                    float unim  = fmaxf(tar + sar[u] - inter, 1e-6f);
                    if (inter > thr * unim) { supc[u] = 1; opc[u] = lf; }
                }
            }
            if (lane == 0) supc[bi] = 1;
            __syncwarp();
        }
    }
}

// ---------------------------------------------------------------------------
extern "C" void kernel_launch(void* const* d_in, const int* in_sizes, int n_in,
                              void* d_out, int out_size) {
    const float4* boxes  = (const float4*)d_in[0];
    const float*  scores = (const float*)d_in[1];
    const float*  iouthr = (const float*)d_in[2];
    const float*  scothr = (const float*)d_in[3];
    float* out = (float*)d_out;

    cudaFuncSetAttribute(mis_kernel, cudaFuncAttributeMaxDynamicSharedMemorySize, MS_SMEM);
    cudaFuncSetAttribute(fb_kernel, cudaFuncAttributeMaxDynamicSharedMemorySize, K3_SMEM);

    sort_kernel<<<BATCH, 1024>>>(boxes);
    adj_kernel<<<BATCH * 128, 512>>>(iouthr);
    mis_kernel<<<BATCH * NC, 1024, MS_SMEM>>>(scores, iouthr, scothr, out);
    fb_kernel<<<BATCH, 1024, K3_SMEM>>>(boxes, scores, iouthr, scothr, out);
}

// round 11
// speedup vs baseline: 1.7519x; 1.2099x over previous
#include <cuda_runtime.h>
#include <cuda_bf16.h>

#define BATCH  4
#define NB     2048
#define NC     4
#define ROWSL  16          // u16 slots per row: [0]=count, [1..15]=neighbors
#define MAXDEG 15
#define NBINS  64

// __device__ scratch (allocation-free rule). uint4 => 32B-aligned rows.
__device__ uint4 g_adj_raw[(size_t)BATCH * NB * ROWSL / 8];
#define G_ADJ ((unsigned short*)g_adj_raw)
__device__ float4         g_sbox[BATCH * NB];      // x1-sorted boxes
__device__ unsigned short g_sidx[BATCH * NB];      // sorted pos -> original idx
__device__ int            g_binoff[BATCH][NBINS + 1];
__device__ float          g_meta[BATCH][3];        // minx, scale, wmax

// ---------------------------------------------------------------------------
// K0: per-batch x1 counting sort into NBINS bins. grid = BATCH, 1024 thr.
// ---------------------------------------------------------------------------
__global__ void __launch_bounds__(1024) sort_kernel(const float4* __restrict__ boxes) {
    __shared__ int   hist[NBINS], cur[NBINS], boff[NBINS + 1];
    __shared__ float rmin[32], rmax[32], rw[32];
    __shared__ float s_minx, s_scale;

    int b = blockIdx.x, tid = threadIdx.x;
    int lane = tid & 31, warp = tid >> 5;
    if (tid < NBINS) { hist[tid] = 0; cur[tid] = 0; }

    const float4* bb = boxes + (size_t)b * NB;
    float4 v0 = bb[tid], v1 = bb[tid + 1024];

    float mn = fminf(v0.x, v1.x);
    float mx = fmaxf(v0.x, v1.x);
    float w  = fmaxf(v0.z - v0.x, v1.z - v1.x);
    #pragma unroll
    for (int o = 16; o; o >>= 1) {
        mn = fminf(mn, __shfl_xor_sync(0xffffffffu, mn, o));
        mx = fmaxf(mx, __shfl_xor_sync(0xffffffffu, mx, o));
        w  = fmaxf(w,  __shfl_xor_sync(0xffffffffu, w,  o));
    }
    if (lane == 0) { rmin[warp] = mn; rmax[warp] = mx; rw[warp] = w; }
    __syncthreads();
    if (warp == 0) {
        mn = rmin[lane]; mx = rmax[lane]; w = rw[lane];
        #pragma unroll
        for (int o = 16; o; o >>= 1) {
            mn = fminf(mn, __shfl_xor_sync(0xffffffffu, mn, o));
            mx = fmaxf(mx, __shfl_xor_sync(0xffffffffu, mx, o));
            w  = fmaxf(w,  __shfl_xor_sync(0xffffffffu, w,  o));
        }
        if (lane == 0) {
            s_minx  = mn;
            s_scale = (float)NBINS / fmaxf(mx - mn, 1e-20f);
            g_meta[b][0] = mn;
            g_meta[b][1] = s_scale;
            g_meta[b][2] = fmaxf(w, 0.0f);
        }
    }
    __syncthreads();

    float minx = s_minx, scale = s_scale;
    int bin0 = min(NBINS - 1, max(0, (int)((v0.x - minx) * scale)));
    int bin1 = min(NBINS - 1, max(0, (int)((v1.x - minx) * scale)));
    atomicAdd(&hist[bin0], 1);
    atomicAdd(&hist[bin1], 1);
    __syncthreads();

    if (tid == 0) {
        int acc = 0;
        for (int k = 0; k < NBINS; k++) { boff[k] = acc; acc += hist[k]; }
        boff[NBINS] = acc;
        for (int k = 0; k <= NBINS; k++) g_binoff[b][k] = boff[k];
    }
    __syncthreads();

    int p0 = boff[bin0] + atomicAdd(&cur[bin0], 1);
    g_sbox[b * NB + p0] = v0;
    g_sidx[b * NB + p0] = (unsigned short)tid;
    int p1 = boff[bin1] + atomicAdd(&cur[bin1], 1);
    g_sbox[b * NB + p1] = v1;
    g_sidx[b * NB + p1] = (unsigned short)(tid + 1024);
}

// ---------------------------------------------------------------------------
// K1: adjacency rows over x1-sorted boxes with bin-window pruning.
// 512 blocks x 512 thr, 16 sorted rows/block. Rows written at ORIGINAL idx.
// ---------------------------------------------------------------------------
__global__ void __launch_bounds__(512) adj_kernel(const float* __restrict__ thrp) {
    __shared__ float sx1[NB], sy1[NB], sx2[NB], sy2[NB], sar[NB];
    __shared__ unsigned short ssidx[NB];
    __shared__ int sboff[NBINS + 1];

    int b    = blockIdx.x >> 7;
    int tile = blockIdx.x & 127;
    int tid  = threadIdx.x;

    const float4* sb = g_sbox + (size_t)b * NB;
    for (int i = tid; i < NB; i += 512) {
        float4 v = sb[i];
        sx1[i] = v.x; sy1[i] = v.y; sx2[i] = v.z; sy2[i] = v.w;
        sar[i] = (v.z - v.x) * (v.w - v.y);
        ssidx[i] = g_sidx[b * NB + i];
    }
    if (tid <= NBINS) sboff[tid] = g_binoff[b][tid];
    __syncthreads();

    float thr  = thrp[0];
    float minx = g_meta[b][0], scale = g_meta[b][1], wmax = g_meta[b][2];
    bool windowed = (thr >= 0.0f);       // hit => x-overlap only valid for thr>=0

    int warp = tid >> 5, lane = tid & 31;
    int p = tile * 16 + warp;            // sorted position of this row

    float rx1 = sx1[p], ry1 = sy1[p], rx2 = sx2[p], ry2 = sy2[p], rar = sar[p];
    int orr = ssidx[p];
    unsigned short* row = G_ADJ + (size_t)(b * NB + orr) * ROWSL;
    int cnt = 0;

    int c0 = 0;
    if (windowed) {
        int bl = (int)((rx1 - wmax - minx) * scale) - 1;   // -1: float slack
        bl = min(NBINS - 1, max(0, bl));
        c0 = sboff[bl] >> 5;
    }

    for (int c = c0; c < NB / 32; c++) {
        if (windowed && sx1[c * 32] > rx2) break;          // sorted: no more overlap
        int u = c * 32 + lane;
        float ix = fminf(rx2, sx2[u]) - fmaxf(rx1, sx1[u]);
        float iy = fminf(ry2, sy2[u]) - fmaxf(ry1, sy1[u]);
        ix = fmaxf(ix, 0.0f);
        iy = fmaxf(iy, 0.0f);
        float inter = ix * iy;
        float unim  = fmaxf(rar + sar[u] - inter, 1e-6f);
        bool hit = (inter > thr * unim) && (u != p);       // drop self by position
        unsigned word = __ballot_sync(0xffffffffu, hit);
        if (lane == 0 && word) {
            int base = c * 32;
            while (word) {
                int j = __ffs(word) - 1;
                word &= word - 1u;
                if (cnt < MAXDEG) row[1 + cnt] = ssidx[base + j];
                cnt++;                                      // exact count even if truncated
            }
        }
    }
    if (lane == 0) row[0] = (unsigned short)cnt;
}

// ---------------------------------------------------------------------------
// K2: lex-first-MIS greedy + integrated exact fallback. grid = BATCH*NC,
// 1024 thr. Rows live in REGISTERS (2 nodes/thread); smem = keys + status.
// One __syncthreads per fixpoint round (monotone over terminal states).
// If any deg > MAXDEG: this block runs the exact serial greedy for its own
// (b,c) over smem-staged boxes (union'd with the main-path smem).
// ---------------------------------------------------------------------------
// smem union layout (bytes):
//   main: skey[2048] u32 @0 (8KB)
//   fb  : sbox[2048] float4 @0 (32KB), sar[2048] @32768 (8KB)
//   both: sst[2048] u8 @40960, scnt[2] int @43008
#define MS_KEY  0
#define MS_SBOX 0
#define MS_SAR  32768
#define MS_ST   40960
#define MS_CNT  43008
#define MS_SMEM 43040

__device__ __forceinline__ unsigned flipkey(float s) {
    unsigned u = __float_as_uint(s);
    return (u & 0x80000000u) ? ~u : (u | 0x80000000u);   // total order on floats
}

__global__ void __launch_bounds__(1024) mis_kernel(const float4* __restrict__ boxes,
                                                   const float* __restrict__ scores,
                                                   const float* __restrict__ thrp,
                                                   const float* __restrict__ sthrp,
                                                   float* __restrict__ out) {
    extern __shared__ unsigned char sm[];
    unsigned*               skey = (unsigned*)(sm + MS_KEY);
    float4*                 fsbox = (float4*)(sm + MS_SBOX);
    float*                  fsar  = (float*)(sm + MS_SAR);
    volatile unsigned char* sst  = sm + MS_ST;
    volatile int*           scnt = (int*)(sm + MS_CNT);

    int bc = blockIdx.x, b = bc >> 2;
    int tid = threadIdx.x, lane = tid & 31, warp = tid >> 5;
    float sthr = sthrp[0];
    bool selfm = thrp[0] < 1.0f;        // self-IoU = 1 claims self iff thr < 1
    const float* spc = scores + (size_t)bc * NB;
    float*       opc = out + (size_t)bc * NB;

    if (tid == 0) scnt[1] = 0;

    // Register rows for this thread's two nodes.
    int n0 = tid, n1 = tid + 1024;
    ushort4 r0[4], r1[4];
    {
        const uint4* g0 = (const uint4*)(G_ADJ + (size_t)(b * NB + n0) * ROWSL);
        const uint4* g1 = (const uint4*)(G_ADJ + (size_t)(b * NB + n1) * ROWSL);
        uint4 a = g0[0], c = g1[0];
        r0[0] = *(ushort4*)&a.x; r0[1] = *(ushort4*)&a.z;   // packs lanes 0..7
        uint4 a2 = g0[1], c2 = g1[1];
        r0[2] = *(ushort4*)&a2.x; r0[3] = *(ushort4*)&a2.z;
        r1[0] = *(ushort4*)&c.x; r1[1] = *(ushort4*)&c.z;
        r1[2] = *(ushort4*)&c2.x; r1[3] = *(ushort4*)&c2.z;
    }
    const unsigned short* e0 = (const unsigned short*)r0;   // e0[0]=deg, e0[1..15]
    const unsigned short* e1 = (const unsigned short*)r1;
    int d0 = e0[0], d1 = e1[0];
    if (d0 > MAXDEG || d1 > MAXDEG) scnt[1] = 1;

    // Init keys, status, trivial outputs.
    float s0 = spc[n0], s1 = spc[n1];
    skey[n0] = flipkey(s0);
    skey[n1] = flipkey(s1);
    unsigned char st0, st1;
    if (s0 > sthr) { if (d0 == 0) { st0 = 3; opc[n0] = selfm ? (float)n0 : -1.0f; } else st0 = 0; }
    else           { st0 = 3; opc[n0] = -1.0f; }
    if (s1 > sthr) { if (d1 == 0) { st1 = 3; opc[n1] = selfm ? (float)n1 : -1.0f; } else st1 = 0; }
    else           { st1 = 3; opc[n1] = -1.0f; }
    sst[n0] = st0;
    sst[n1] = st1;
    __syncthreads();

    if (scnt[1] == 0) {
        // ---- main path: fixpoint, ONE barrier per round ----
        bool u0 = (st0 == 0), u1 = (st1 == 0);
        for (int round = 0; round < 4096; round++) {
            if (u0) {
                unsigned mk = skey[n0];
                bool blocked = false, claimed = false;
                #pragma unroll
                for (int e = 1; e <= MAXDEG; e++) {
                    if (e > d0) break;
                    int u = e0[e];
                    unsigned char stu = sst[u];
                    if (stu >= 2) continue;
                    unsigned fu = skey[u];
                    bool hp = (fu > mk) || (fu == mk && u < n0);
                    if (!hp) continue;
                    if (stu == 1) { claimed = true; break; }
                    blocked = true;
                }
                if (claimed)       { sst[n0] = 2; u0 = false; }
                else if (!blocked) { sst[n0] = 1; u0 = false; }
            }
            if (u1) {
                unsigned mk = skey[n1];
                bool blocked = false, claimed = false;
                #pragma unroll
                for (int e = 1; e <= MAXDEG; e++) {
                    if (e > d1) break;
                    int u = e1[e];
                    unsigned char stu = sst[u];
                    if (stu >= 2) continue;
                    unsigned fu = skey[u];
                    bool hp = (fu > mk) || (fu == mk && u < n1);
                    if (!hp) continue;
                    if (stu == 1) { claimed = true; break; }
                    blocked = true;
                }
                if (claimed)       { sst[n1] = 2; u1 = false; }
                else if (!blocked) { sst[n1] = 1; u1 = false; }
            }
            if (u0 | u1) scnt[0] = round + 1;        // benign race: same value
            __syncthreads();
            if (scnt[0] != round + 1) break;
        }

        // ---- final assignment (claimed -> best adjacent leader) ----
        unsigned char f0 = sst[n0], f1 = sst[n1];
        if (f0 == 1) opc[n0] = (float)n0;
        else if (f0 == 2) {
            unsigned bk = 0; int bu = -1;
            #pragma unroll
            for (int e = 1; e <= MAXDEG; e++) {
                if (e > d0) break;
                int u = e0[e];
                if (sst[u] == 1) {
                    unsigned fu = skey[u];
                    if (bu < 0 || fu > bk || (fu == bk && u < bu)) { bk = fu; bu = u; }
                }
            }
            opc[n0] = (float)bu;
        }
        if (f1 == 1) opc[n1] = (float)n1;
        else if (f1 == 2) {
            unsigned bk = 0; int bu = -1;
            #pragma unroll
            for (int e = 1; e <= MAXDEG; e++) {
                if (e > d1) break;
                int u = e1[e];
                if (sst[u] == 1) {
                    unsigned fu = skey[u];
                    if (bu < 0 || fu > bk || (fu == bk && u < bu)) { bk = fu; bu = u; }
                }
            }
            opc[n1] = (float)bu;
        }
        return;
    }

    // ---- integrated exact fallback for THIS (b,c) (adversarial only) ----
    {
        float thr = thrp[0];
        const float4* bb = boxes + (size_t)b * NB;
        for (int i = tid; i < NB; i += 1024) {
            float4 v = bb[i];
            fsbox[i] = v;
            fsar[i] = (v.z - v.x) * (v.w - v.y);
        }
        for (int n = tid; n < NB; n += 1024) {
            sst[n] = (spc[n] > sthr) ? 0 : 1;
            opc[n] = -1.0f;
        }
        __syncthreads();

        if (warp == 0) {
            for (;;) {
                float bs = -1e30f; int bi = 1 << 30;
                for (int k = 0; k < NB / 32; k++) {
                    int u = k * 32 + lane;
                    if (!sst[u]) {
                        float s = spc[u];
                        if (s > bs || (s == bs && u < bi)) { bs = s; bi = u; }
                    }
                }
                #pragma unroll
                for (int off = 16; off; off >>= 1) {
                    float os = __shfl_down_sync(0xffffffffu, bs, off);
                    int   oi = __shfl_down_sync(0xffffffffu, bi, off);
                    if (os > bs || (os == bs && oi < bi)) { bs = os; bi = oi; }
                }
                bi = __shfl_sync(0xffffffffu, bi, 0);
                if (bi >= (1 << 30)) break;

                float4 tb = fsbox[bi];
                float tar = fsar[bi];
                float lf = (float)bi;
                for (int k = 0; k < NB / 32; k++) {
                    int u = k * 32 + lane;
                    if (!sst[u]) {
                        float4 ub = fsbox[u];
                        float ix = fminf(tb.z, ub.z) - fmaxf(tb.x, ub.x);
                        float iy = fminf(tb.w, ub.w) - fmaxf(tb.y, ub.y);
                        ix = fmaxf(ix, 0.0f);
                        iy = fmaxf(iy, 0.0f);
                        float inter = ix * iy;
                        float unim  = fmaxf(tar + fsar[u] - inter, 1e-6f);
                        if (inter > thr * unim) { sst[u] = 1; opc[u] = lf; }
                    }
                }
                if (lane == 0) sst[bi] = 1;
                __syncwarp();
            }
        }
    }
}

// ---------------------------------------------------------------------------
extern "C" void kernel_launch(void* const* d_in, const int* in_sizes, int n_in,
                              void* d_out, int out_size) {
    const float4* boxes  = (const float4*)d_in[0];
    const float*  scores = (const float*)d_in[1];
    const float*  iouthr = (const float*)d_in[2];
    const float*  scothr = (const float*)d_in[3];
    float* out = (float*)d_out;

    cudaFuncSetAttribute(mis_kernel, cudaFuncAttributeMaxDynamicSharedMemorySize, MS_SMEM);

    sort_kernel<<<BATCH, 1024>>>(boxes);
    adj_kernel<<<BATCH * 128, 512>>>(iouthr);
    mis_kernel<<<BATCH * NC, 1024, MS_SMEM>>>(boxes, scores, iouthr, scothr, out);
}

// round 12
// speedup vs baseline: 2.4316x; 1.3880x over previous
#include <cuda_runtime.h>
#include <cuda_bf16.h>

#define BATCH  4
#define NB     2048
#define NC     4
#define ROWSL  16          // u16 slots per row: [0]=count, [1..15]=neighbors
#define MAXDEG 15
#define NBINS  64

// __device__ scratch (allocation-free rule). uint4 => 32B-aligned rows.
__device__ uint4 g_adj_raw[(size_t)BATCH * NB * ROWSL / 8];
#define G_ADJ ((unsigned short*)g_adj_raw)
__device__ float4         g_sbox[BATCH * NB];      // bin-sorted boxes (by x1)
__device__ unsigned short g_sidx[BATCH * NB];      // sorted pos -> original idx
__device__ int            g_binoff[BATCH][NBINS + 1];
__device__ float          g_meta[BATCH][4];        // minx, scale, wmax, binw

// ---------------------------------------------------------------------------
// K0: per-batch x1 counting sort into NBINS bins. grid = BATCH, 1024 thr.
// Per-warp privatized histograms + cursors: atomic contention <= intra-warp.
// ---------------------------------------------------------------------------
__global__ void __launch_bounds__(1024) sort_kernel(const float4* __restrict__ boxes) {
    __shared__ int   wh[32 * 64];     // per-warp hist -> column-exclusive base
    __shared__ int   wcur[32 * 64];   // absolute scatter cursors
    __shared__ int   hist64[64];
    __shared__ int   boff[NBINS + 1];
    __shared__ float rmin[32], rmax[32], rw[32];
    __shared__ float s_minx, s_scale;

    int b = blockIdx.x, tid = threadIdx.x;
    int lane = tid & 31, warp = tid >> 5;

    wh[tid] = 0; wh[tid + 1024] = 0;

    const float4* bb = boxes + (size_t)b * NB;
    float4 v0 = bb[tid], v1 = bb[tid + 1024];

    // block reduce: min x1, max x1, max width
    float mn = fminf(v0.x, v1.x);
    float mx = fmaxf(v0.x, v1.x);
    float w  = fmaxf(v0.z - v0.x, v1.z - v1.x);
    #pragma unroll
    for (int o = 16; o; o >>= 1) {
        mn = fminf(mn, __shfl_xor_sync(0xffffffffu, mn, o));
        mx = fmaxf(mx, __shfl_xor_sync(0xffffffffu, mx, o));
        w  = fmaxf(w,  __shfl_xor_sync(0xffffffffu, w,  o));
    }
    if (lane == 0) { rmin[warp] = mn; rmax[warp] = mx; rw[warp] = w; }
    __syncthreads();
    if (warp == 0) {
        mn = rmin[lane]; mx = rmax[lane]; w = rw[lane];
        #pragma unroll
        for (int o = 16; o; o >>= 1) {
            mn = fminf(mn, __shfl_xor_sync(0xffffffffu, mn, o));
            mx = fmaxf(mx, __shfl_xor_sync(0xffffffffu, mx, o));
            w  = fmaxf(w,  __shfl_xor_sync(0xffffffffu, w,  o));
        }
        if (lane == 0) {
            float span = fmaxf(mx - mn, 1e-20f);
            s_minx  = mn;
            s_scale = (float)NBINS / span;
            g_meta[b][0] = mn;
            g_meta[b][1] = s_scale;
            g_meta[b][2] = fmaxf(w, 0.0f);
            g_meta[b][3] = span / (float)NBINS;     // bin width
        }
    }
    __syncthreads();

    float minx = s_minx, scale = s_scale;
    int bin0 = min(NBINS - 1, max(0, (int)((v0.x - minx) * scale)));
    int bin1 = min(NBINS - 1, max(0, (int)((v1.x - minx) * scale)));
    atomicAdd(&wh[warp * 64 + bin0], 1);            // intra-warp contention only
    atomicAdd(&wh[warp * 64 + bin1], 1);
    __syncthreads();

    // Column scan: per-bin totals + per-warp exclusive base (within bin).
    if (tid < 64) {
        int acc = 0;
        #pragma unroll 8
        for (int wdx = 0; wdx < 32; wdx++) {
            int t = wh[wdx * 64 + tid];
            wcur[wdx * 64 + tid] = acc;
            acc += t;
        }
        hist64[tid] = acc;
    }
    __syncthreads();

    // Warp-scan prefix over 64 bin totals.
    if (warp == 0) {
        int a0 = hist64[lane], a1 = hist64[lane + 32];
        #pragma unroll
        for (int o = 1; o < 32; o <<= 1) {
            int n = __shfl_up_sync(0xffffffffu, a0, o);
            if (lane >= o) a0 += n;
        }
        int tot0 = __shfl_sync(0xffffffffu, a0, 31);
        #pragma unroll
        for (int o = 1; o < 32; o <<= 1) {
            int n = __shfl_up_sync(0xffffffffu, a1, o);
            if (lane >= o) a1 += n;
        }
        a1 += tot0;
        if (lane == 0) { boff[0] = 0; g_binoff[b][0] = 0; }
        boff[lane + 1] = a0;       g_binoff[b][lane + 1] = a0;
        boff[lane + 33] = a1;      g_binoff[b][lane + 33] = a1;
    }
    __syncthreads();

    // Absolute cursors = global bin offset + per-warp column base.
    wcur[tid]        += boff[tid & 63];
    wcur[tid + 1024] += boff[tid & 63];
    __syncthreads();

    int p0 = atomicAdd(&wcur[warp * 64 + bin0], 1);
    g_sbox[b * NB + p0] = v0;
    g_sidx[b * NB + p0] = (unsigned short)tid;
    int p1 = atomicAdd(&wcur[warp * 64 + bin1], 1);
    g_sbox[b * NB + p1] = v1;
    g_sidx[b * NB + p1] = (unsigned short)(tid + 1024);
}

// ---------------------------------------------------------------------------
// K1: adjacency rows over bin-sorted boxes. 512 blocks x 512 thr, 16 rows.
// Stages ONLY the x-window these 16 rows can touch. Break is BIN-SAFE:
// within a bin x1 is unordered, so we break on the bin's lower bound (with
// one-bin slack), a true lower bound for all remaining elements.
// Rows written at ORIGINAL indices.
// ---------------------------------------------------------------------------
__global__ void __launch_bounds__(512) adj_kernel(const float* __restrict__ thrp) {
    __shared__ float sx1[NB], sy1[NB], sx2[NB], sy2[NB], sar[NB];
    __shared__ unsigned short ssidx[NB];
    __shared__ int sboff[NBINS + 1];
    __shared__ float4 rowbox[16];
    __shared__ int s_lo, s_hi;

    int b    = blockIdx.x >> 7;
    int tile = blockIdx.x & 127;
    int tid  = threadIdx.x;
    int warp = tid >> 5, lane = tid & 31;

    float thr  = thrp[0];
    float minx = g_meta[b][0], scale = g_meta[b][1];
    float wmax = g_meta[b][2], binw = g_meta[b][3];
    bool windowed = (thr >= 0.0f);       // hit => x-overlap only valid for thr>=0

    if (tid <= NBINS) sboff[tid] = g_binoff[b][tid];
    if (tid < 16) rowbox[tid] = g_sbox[b * NB + tile * 16 + tid];
    __syncthreads();

    // Window for this block's 16 rows.
    if (warp == 0) {
        float4 rv = rowbox[lane & 15];
        float r1 = rv.x, r2 = rv.z;
        #pragma unroll
        for (int o = 16; o; o >>= 1) {
            r1 = fminf(r1, __shfl_xor_sync(0xffffffffu, r1, o));
            r2 = fmaxf(r2, __shfl_xor_sync(0xffffffffu, r2, o));
        }
        if (lane == 0) {
            int lo = 0, hi = NB;
            if (windowed) {
                int bl = min(NBINS - 1, max(0, (int)((r1 - wmax - minx) * scale) - 1));
                int bh = min(NBINS, max(1, (int)((r2 - minx) * scale) + 2));
                lo = sboff[bl] & ~31;
                hi = min(NB, (sboff[bh] + 31) & ~31);
            }
            s_lo = lo; s_hi = hi;
        }
    }
    __syncthreads();
    int lo = s_lo, hi = s_hi;

    // Stage the window.
    const float4* sb = g_sbox + (size_t)b * NB;
    for (int i = lo + tid; i < hi; i += 512) {
        float4 v = sb[i];
        int k = i - lo;
        sx1[k] = v.x; sy1[k] = v.y; sx2[k] = v.z; sy2[k] = v.w;
        sar[k] = (v.z - v.x) * (v.w - v.y);
        ssidx[k] = g_sidx[b * NB + i];
    }
    __syncthreads();

    int p = tile * 16 + warp;            // sorted position of this row (16 warps)
    float4 rv = rowbox[warp];
    float rx1 = rv.x, ry1 = rv.y, rx2 = rv.z, ry2 = rv.w;
    float rar = (rx2 - rx1) * (ry2 - ry1);
    int orr = ssidx[p - lo];
    unsigned short* row = G_ADJ + (size_t)(b * NB + orr) * ROWSL;
    int cnt = 0;

    int c0 = lo >> 5;
    if (windowed) {
        int bl = min(NBINS - 1, max(0, (int)((rx1 - wmax - minx) * scale) - 1));
        c0 = max(c0, sboff[bl] >> 5);
    }

    for (int c = c0; c < (hi >> 5); c++) {
        if (windowed) {
            // bin-safe break: all remaining elements have x1 >= binlo(bc)-slack
            float x1c = sx1[c * 32 - lo];
            int bc = min(NBINS - 1, max(0, (int)((x1c - minx) * scale)));
            if (minx + (float)(bc - 1) * binw > rx2) break;
        }
        int k = c * 32 + lane - lo;
        float ix = fminf(rx2, sx2[k]) - fmaxf(rx1, sx1[k]);
        float iy = fminf(ry2, sy2[k]) - fmaxf(ry1, sy1[k]);
        ix = fmaxf(ix, 0.0f);
        iy = fmaxf(iy, 0.0f);
        float inter = ix * iy;
        float unim  = fmaxf(rar + sar[k] - inter, 1e-6f);
        bool hit = (inter > thr * unim) && (c * 32 + lane != p);   // drop self
        unsigned word = __ballot_sync(0xffffffffu, hit);
        if (lane == 0 && word) {
            int base = c * 32 - lo;
            while (word) {
                int j = __ffs(word) - 1;
                word &= word - 1u;
                if (cnt < MAXDEG) row[1 + cnt] = ssidx[base + j];
                cnt++;                                  // exact count even if truncated
            }
        }
    }
    if (lane == 0) row[0] = (unsigned short)cnt;
}

// ---------------------------------------------------------------------------
// K2: lex-first-MIS greedy + integrated exact fallback. grid = BATCH*NC,
// 1024 thr. Rows in registers (2 nodes/thread); one barrier per round.
// ---------------------------------------------------------------------------
#define MS_KEY  0
#define MS_SBOX 0
#define MS_SAR  32768
#define MS_ST   40960
#define MS_CNT  43008
#define MS_SMEM 43040

__device__ __forceinline__ unsigned flipkey(float s) {
    unsigned u = __float_as_uint(s);
    return (u & 0x80000000u) ? ~u : (u | 0x80000000u);   // total order on floats
}

__global__ void __launch_bounds__(1024) mis_kernel(const float4* __restrict__ boxes,
                                                   const float* __restrict__ scores,
                                                   const float* __restrict__ thrp,
                                                   const float* __restrict__ sthrp,
                                                   float* __restrict__ out) {
    extern __shared__ unsigned char sm[];
    unsigned*               skey  = (unsigned*)(sm + MS_KEY);
    float4*                 fsbox = (float4*)(sm + MS_SBOX);
    float*                  fsar  = (float*)(sm + MS_SAR);
    volatile unsigned char* sst   = sm + MS_ST;
    volatile int*           scnt  = (int*)(sm + MS_CNT);

    int bc = blockIdx.x, b = bc >> 2;
    int tid = threadIdx.x, lane = tid & 31, warp = tid >> 5;
    float sthr = sthrp[0];
    bool selfm = thrp[0] < 1.0f;        // self-IoU = 1 claims self iff thr < 1
    const float* spc = scores + (size_t)bc * NB;
    float*       opc = out + (size_t)bc * NB;

    if (tid == 0) scnt[1] = 0;

    int n0 = tid, n1 = tid + 1024;
    ushort4 r0[4], r1[4];
    {
        const uint4* g0 = (const uint4*)(G_ADJ + (size_t)(b * NB + n0) * ROWSL);
        const uint4* g1 = (const uint4*)(G_ADJ + (size_t)(b * NB + n1) * ROWSL);
        uint4 a = g0[0], c = g1[0];
        r0[0] = *(ushort4*)&a.x; r0[1] = *(ushort4*)&a.z;
        uint4 a2 = g0[1], c2 = g1[1];
        r0[2] = *(ushort4*)&a2.x; r0[3] = *(ushort4*)&a2.z;
        r1[0] = *(ushort4*)&c.x; r1[1] = *(ushort4*)&c.z;
        r1[2] = *(ushort4*)&c2.x; r1[3] = *(ushort4*)&c2.z;
    }
    const unsigned short* e0 = (const unsigned short*)r0;
    const unsigned short* e1 = (const unsigned short*)r1;
    int d0 = e0[0], d1 = e1[0];
    if (d0 > MAXDEG || d1 > MAXDEG) scnt[1] = 1;

    float s0 = spc[n0], s1 = spc[n1];
    skey[n0] = flipkey(s0);
    skey[n1] = flipkey(s1);
    unsigned char st0, st1;
    if (s0 > sthr) { if (d0 == 0) { st0 = 3; opc[n0] = selfm ? (float)n0 : -1.0f; } else st0 = 0; }
    else           { st0 = 3; opc[n0] = -1.0f; }
    if (s1 > sthr) { if (d1 == 0) { st1 = 3; opc[n1] = selfm ? (float)n1 : -1.0f; } else st1 = 0; }
    else           { st1 = 3; opc[n1] = -1.0f; }
    sst[n0] = st0;
    sst[n1] = st1;
    __syncthreads();

    if (scnt[1] == 0) {
        bool u0 = (st0 == 0), u1 = (st1 == 0);
        for (int round = 0; round < 4096; round++) {
            if (u0) {
                unsigned mk = skey[n0];
                bool blocked = false, claimed = false;
                #pragma unroll
                for (int e = 1; e <= MAXDEG; e++) {
                    if (e > d0) break;
                    int u = e0[e];
                    unsigned char stu = sst[u];
                    if (stu >= 2) continue;
                    unsigned fu = skey[u];
                    bool hp = (fu > mk) || (fu == mk && u < n0);
                    if (!hp) continue;
                    if (stu == 1) { claimed = true; break; }
                    blocked = true;
                }
                if (claimed)       { sst[n0] = 2; u0 = false; }
                else if (!blocked) { sst[n0] = 1; u0 = false; }
            }
            if (u1) {
                unsigned mk = skey[n1];
                bool blocked = false, claimed = false;
                #pragma unroll
                for (int e = 1; e <= MAXDEG; e++) {
                    if (e > d1) break;
                    int u = e1[e];
                    unsigned char stu = sst[u];
                    if (stu >= 2) continue;
                    unsigned fu = skey[u];
                    bool hp = (fu > mk) || (fu == mk && u < n1);
                    if (!hp) continue;
                    if (stu == 1) { claimed = true; break; }
                    blocked = true;
                }
                if (claimed)       { sst[n1] = 2; u1 = false; }
                else if (!blocked) { sst[n1] = 1; u1 = false; }
            }
            if (u0 | u1) scnt[0] = round + 1;        // benign race: same value
            __syncthreads();
            if (scnt[0] != round + 1) break;
        }

        unsigned char f0 = sst[n0], f1 = sst[n1];
        if (f0 == 1) opc[n0] = (float)n0;
        else if (f0 == 2) {
            unsigned bk = 0; int bu = -1;
            #pragma unroll
            for (int e = 1; e <= MAXDEG; e++) {
                if (e > d0) break;
                int u = e0[e];
                if (sst[u] == 1) {
                    unsigned fu = skey[u];
                    if (bu < 0 || fu > bk || (fu == bk && u < bu)) { bk = fu; bu = u; }
                }
            }
            opc[n0] = (float)bu;
        }
        if (f1 == 1) opc[n1] = (float)n1;
        else if (f1 == 2) {
            unsigned bk = 0; int bu = -1;
            #pragma unroll
            for (int e = 1; e <= MAXDEG; e++) {
                if (e > d1) break;
                int u = e1[e];
                if (sst[u] == 1) {
                    unsigned fu = skey[u];
                    if (bu < 0 || fu > bk || (fu == bk && u < bu)) { bk = fu; bu = u; }
                }
            }
            opc[n1] = (float)bu;
        }
        return;
    }

    // ---- integrated exact fallback for THIS (b,c) (adversarial only) ----
    {
        float thr = thrp[0];
        const float4* bb = boxes + (size_t)b * NB;
        for (int i = tid; i < NB; i += 1024) {
            float4 v = bb[i];
            fsbox[i] = v;
            fsar[i] = (v.z - v.x) * (v.w - v.y);
        }
        for (int n = tid; n < NB; n += 1024) {
            sst[n] = (spc[n] > sthr) ? 0 : 1;
            opc[n] = -1.0f;
        }
        __syncthreads();

        if (warp == 0) {
            for (;;) {
                float bs = -1e30f; int bi = 1 << 30;
                for (int k = 0; k < NB / 32; k++) {
                    int u = k * 32 + lane;
                    if (!sst[u]) {
                        float s = spc[u];
                        if (s > bs || (s == bs && u < bi)) { bs = s; bi = u; }
                    }
                }
                #pragma unroll
                for (int off = 16; off; off >>= 1) {
                    float os = __shfl_down_sync(0xffffffffu, bs, off);
                    int   oi = __shfl_down_sync(0xffffffffu, bi, off);
                    if (os > bs || (os == bs && oi < bi)) { bs = os; bi = oi; }
                }
                bi = __shfl_sync(0xffffffffu, bi, 0);
                if (bi >= (1 << 30)) break;

                float4 tb = fsbox[bi];
                float tar = fsar[bi];
                float lf = (float)bi;
                for (int k = 0; k < NB / 32; k++) {
                    int u = k * 32 + lane;
                    if (!sst[u]) {
                        float4 ub = fsbox[u];
                        float ix = fminf(tb.z, ub.z) - fmaxf(tb.x, ub.x);
                        float iy = fminf(tb.w, ub.w) - fmaxf(tb.y, ub.y);
                        ix = fmaxf(ix, 0.0f);
                        iy = fmaxf(iy, 0.0f);
                        float inter = ix * iy;
                        float unim  = fmaxf(tar + fsar[u] - inter, 1e-6f);
                        if (inter > thr * unim) { sst[u] = 1; opc[u] = lf; }
                    }
                }
                if (lane == 0) sst[bi] = 1;
                __syncwarp();
            }
        }
    }
}

// ---------------------------------------------------------------------------
extern "C" void kernel_launch(void* const* d_in, const int* in_sizes, int n_in,
                              void* d_out, int out_size) {
    const float4* boxes  = (const float4*)d_in[0];
    const float*  scores = (const float*)d_in[1];
    const float*  iouthr = (const float*)d_in[2];
    const float*  scothr = (const float*)d_in[3];
    float* out = (float*)d_out;

    cudaFuncSetAttribute(mis_kernel, cudaFuncAttributeMaxDynamicSharedMemorySize, MS_SMEM);

    sort_kernel<<<BATCH, 1024>>>(boxes);
    adj_kernel<<<BATCH * 128, 512>>>(iouthr);
    mis_kernel<<<BATCH * NC, 1024, MS_SMEM>>>(boxes, scores, iouthr, scothr, out);
}